// round 1
// baseline (speedup 1.0000x reference)
#include <cuda_runtime.h>
#include <cuda_bf16.h>
#include <mma.h>
#include <cstddef>

using namespace nvcuda;

#define BB    32
#define TKK   1024
#define HH    512
#define EE    256
#define VOCAB 50257
#define M_ENC (BB * TKK)   // 32768

// ---------------- scratch (__device__ globals: allocation-guard safe) --------
__device__ float g_xin[BB * (HH + EE)];
__device__ float g_x[BB * EE];
__device__ float g_gi[BB * 3 * HH];
__device__ float g_gh[BB * 3 * HH];
__device__ float g_hnew[BB * HH];
__device__ float g_dec[BB * HH];
__device__ float g_encfeat[(size_t)M_ENC * HH];        // 64 MB
__device__ float g_scores[BB * TKK];
__device__ float g_cpart[BB * 16 * HH];
__device__ float g_concat[BB * 2 * HH];
__device__ float g_out1[BB * HH];
__device__ float g_logits[(size_t)BB * VOCAB];         // 6.4 MB

// ---------------- small helpers ---------------------------------------------
__device__ __forceinline__ float sigmoidf_(float x) { return 1.f / (1.f + expf(-x)); }

// ---------------- K1: build [c_t_1 | emb[y]] --------------------------------
__global__ void k_build_xin(const int* __restrict__ yt,
                            const float* __restrict__ c_t_1,
                            const float* __restrict__ emb) {
    int b = blockIdx.x;
    int yid = yt[b];
    for (int i = threadIdx.x; i < HH; i += blockDim.x)
        g_xin[b * (HH + EE) + i] = c_t_1[b * HH + i];
    for (int i = threadIdx.x; i < EE; i += blockDim.x)
        g_xin[b * (HH + EE) + HH + i] = emb[(size_t)yid * EE + i];
}

// ---------------- generic y[b,n] = bias[n] + A[b,:] . W[n,:] ----------------
__global__ void k_dots(float* __restrict__ y, const float* __restrict__ A,
                       const float* __restrict__ W, const float* __restrict__ bias,
                       int N, int K) {
    __shared__ float sA[1024];
    int b = blockIdx.y;
    for (int i = threadIdx.x; i < K; i += blockDim.x) sA[i] = A[(size_t)b * K + i];
    __syncthreads();
    int n = blockIdx.x * blockDim.x + threadIdx.x;
    if (n >= N) return;
    const float4* w4 = (const float4*)(W + (size_t)n * K);
    const float4* a4 = (const float4*)sA;
    float acc = 0.f;
    int K4 = K >> 2;
#pragma unroll 4
    for (int i = 0; i < K4; i++) {
        float4 w = w4[i];
        float4 a = a4[i];
        acc += w.x * a.x + w.y * a.y + w.z * a.z + w.w * a.w;
    }
    y[(size_t)b * N + n] = acc + bias[n];
}

// ---------------- GRU gate combine ------------------------------------------
__global__ void k_gru(const float* __restrict__ hprev, float* __restrict__ out_st) {
    int b = blockIdx.x, j = threadIdx.x;   // 512 threads
    const float* gi = g_gi + b * 3 * HH;
    const float* gh = g_gh + b * 3 * HH;
    float r  = sigmoidf_(gi[j] + gh[j]);
    float z  = sigmoidf_(gi[HH + j] + gh[HH + j]);
    float nn = tanhf(gi[2 * HH + j] + r * gh[2 * HH + j]);
    float h  = hprev[b * HH + j];
    float hn = (1.f - z) * nn + z * h;
    g_hnew[b * HH + j] = hn;
    out_st[b * HH + j] = hn;
}

// ---------------- big GEMM: enc_feat = enc @ Wh^T  (bf16 wmma, fp32 acc) ----
__global__ __launch_bounds__(128) void k_encfeat(const float* __restrict__ A,
                                                 const float* __restrict__ Bw) {
    __shared__ __nv_bfloat16 As[64][48];   // ldm 48 elems = 96B (32B aligned)
    __shared__ __nv_bfloat16 Bs[64][48];
    int tid = threadIdx.x;                 // 128
    int m0 = blockIdx.y * 64, n0 = blockIdx.x * 64;
    int w = tid >> 5, wm = w >> 1, wn = w & 1;

    wmma::fragment<wmma::accumulator, 16, 16, 16, float> acc[2][2];
#pragma unroll
    for (int i = 0; i < 2; i++)
#pragma unroll
        for (int j = 0; j < 2; j++) wmma::fill_fragment(acc[i][j], 0.f);

    for (int k0 = 0; k0 < HH; k0 += 32) {
#pragma unroll
        for (int i = 0; i < 4; i++) {
            int lin = tid + i * 128;           // 0..511
            int row = lin >> 3, q = lin & 7;   // 64 rows x 8 quads
            float4 va = *(const float4*)(A + (size_t)(m0 + row) * HH + k0 + q * 4);
            *(__nv_bfloat162*)&As[row][q * 4]     = __floats2bfloat162_rn(va.x, va.y);
            *(__nv_bfloat162*)&As[row][q * 4 + 2] = __floats2bfloat162_rn(va.z, va.w);
            float4 vb = *(const float4*)(Bw + (size_t)(n0 + row) * HH + k0 + q * 4);
            *(__nv_bfloat162*)&Bs[row][q * 4]     = __floats2bfloat162_rn(vb.x, vb.y);
            *(__nv_bfloat162*)&Bs[row][q * 4 + 2] = __floats2bfloat162_rn(vb.z, vb.w);
        }
        __syncthreads();
#pragma unroll
        for (int kk = 0; kk < 32; kk += 16) {
            wmma::fragment<wmma::matrix_a, 16, 16, 16, __nv_bfloat16, wmma::row_major> af[2];
            wmma::fragment<wmma::matrix_b, 16, 16, 16, __nv_bfloat16, wmma::col_major> bf[2];
#pragma unroll
            for (int i = 0; i < 2; i++)
                wmma::load_matrix_sync(af[i], &As[wm * 32 + i * 16][kk], 48);
#pragma unroll
            for (int j = 0; j < 2; j++)
                wmma::load_matrix_sync(bf[j], &Bs[wn * 32 + j * 16][kk], 48);
#pragma unroll
            for (int i = 0; i < 2; i++)
#pragma unroll
                for (int j = 0; j < 2; j++)
                    wmma::mma_sync(acc[i][j], af[i], bf[j], acc[i][j]);
        }
        __syncthreads();
    }
#pragma unroll
    for (int i = 0; i < 2; i++)
#pragma unroll
        for (int j = 0; j < 2; j++)
            wmma::store_matrix_sync(
                g_encfeat + (size_t)(m0 + wm * 32 + i * 16) * HH + n0 + wn * 32 + j * 16,
                acc[i][j], HH, wmma::mem_row_major);
}

// ---------------- scores[b,t] = v . tanh(enc_feat[b,t,:] + dec[b,:]) --------
__global__ void k_scores(const float* __restrict__ vw) {
    int warp = (blockIdx.x * blockDim.x + threadIdx.x) >> 5;
    int lane = threadIdx.x & 31;
    if (warp >= M_ENC) return;
    int b = warp >> 10;
    const float* ef  = g_encfeat + (size_t)warp * HH;
    const float* dec = g_dec + b * HH;
    float acc = 0.f;
#pragma unroll
    for (int j = 0; j < 16; j++) {
        int k = j * 32 + lane;
        acc += vw[k] * tanhf(ef[k] + dec[k]);
    }
#pragma unroll
    for (int o = 16; o; o >>= 1) acc += __shfl_down_sync(0xffffffffu, acc, o);
    if (lane == 0) g_scores[warp] = acc;
}

// ---------------- softmax over TK per b -------------------------------------
__global__ void k_attn(float* __restrict__ out_attn) {
    __shared__ float red[32];
    int b = blockIdx.x, t = threadIdx.x;   // 1024 threads
    float s = g_scores[b * TKK + t];

    float m = s;
#pragma unroll
    for (int o = 16; o; o >>= 1) m = fmaxf(m, __shfl_xor_sync(0xffffffffu, m, o));
    if ((t & 31) == 0) red[t >> 5] = m;
    __syncthreads();
    if (t < 32) {
        float v = red[t];
#pragma unroll
        for (int o = 16; o; o >>= 1) v = fmaxf(v, __shfl_xor_sync(0xffffffffu, v, o));
        if (t == 0) red[0] = v;
    }
    __syncthreads();
    float mx = red[0];
    __syncthreads();

    float e = expf(s - mx);
    float sm = e;
#pragma unroll
    for (int o = 16; o; o >>= 1) sm += __shfl_xor_sync(0xffffffffu, sm, o);
    if ((t & 31) == 0) red[t >> 5] = sm;
    __syncthreads();
    if (t < 32) {
        float v = red[t];
#pragma unroll
        for (int o = 16; o; o >>= 1) v += __shfl_xor_sync(0xffffffffu, v, o);
        if (t == 0) red[0] = v;
    }
    __syncthreads();
    out_attn[b * TKK + t] = e * (1.f / red[0]);
}

// ---------------- c_t partials: 16 t-chunks of 64 ---------------------------
__global__ void k_ct_part(const float* __restrict__ enc, const float* __restrict__ attn) {
    __shared__ float sa[64];
    int c = blockIdx.x, b = blockIdx.y, h = threadIdx.x;   // 512 threads
    if (h < 64) sa[h] = attn[b * TKK + c * 64 + h];
    __syncthreads();
    const float* e = enc + ((size_t)b * TKK + c * 64) * HH + h;
    float acc = 0.f;
#pragma unroll 8
    for (int t = 0; t < 64; t++) acc += sa[t] * e[(size_t)t * HH];
    g_cpart[((size_t)b * 16 + c) * HH + h] = acc;
}

// ---------------- c_t reduce + build concat(h_new, c_t) ---------------------
__global__ void k_ct_fin(float* __restrict__ out_ct) {
    int b = blockIdx.x, h = threadIdx.x;   // 512
    float acc = 0.f;
#pragma unroll
    for (int c = 0; c < 16; c++) acc += g_cpart[((size_t)b * 16 + c) * HH + h];
    out_ct[b * HH + h] = acc;
    g_concat[b * 2 * HH + h] = g_hnew[b * HH + h];
    g_concat[b * 2 * HH + HH + h] = acc;
}

// ---------------- logits: all 32 b per thread-n -----------------------------
__global__ __launch_bounds__(256) void k_logits(const float* __restrict__ W,
                                                const float* __restrict__ bias) {
    extern __shared__ float sO[];          // [512][32] fp32 (k-major, b inner)
    int tid = threadIdx.x;                 // 256
    for (int i = tid; i < BB * HH; i += 256) {
        int b = i >> 9, k = i & 511;
        sO[k * 32 + b] = g_out1[i];
    }
    __syncthreads();
    int n = blockIdx.x * 256 + tid;
    if (n >= VOCAB) return;
    const float4* w4 = (const float4*)(W + (size_t)n * HH);
    float acc[32];
#pragma unroll
    for (int b = 0; b < 32; b++) acc[b] = 0.f;
    for (int k4 = 0; k4 < HH / 4; k4++) {
        float4 wv = w4[k4];
        const float* s0 = sO + (k4 * 4) * 32;
#pragma unroll
        for (int b = 0; b < 32; b++) acc[b] += wv.x * s0[b];
#pragma unroll
        for (int b = 0; b < 32; b++) acc[b] += wv.y * s0[32 + b];
#pragma unroll
        for (int b = 0; b < 32; b++) acc[b] += wv.z * s0[64 + b];
#pragma unroll
        for (int b = 0; b < 32; b++) acc[b] += wv.w * s0[96 + b];
    }
    float bb = bias[n];
#pragma unroll
    for (int b = 0; b < 32; b++) g_logits[(size_t)b * VOCAB + n] = acc[b] + bb;
}

// ---------------- softmax over V per b --------------------------------------
__global__ void k_softmaxV(float* __restrict__ out_fd) {
    __shared__ float red[32];
    int b = blockIdx.x, tid = threadIdx.x;     // 512 threads
    const float* lg = g_logits + (size_t)b * VOCAB;
    float* dst = out_fd + (size_t)b * VOCAB;

    float m = -1e30f;
    for (int n = tid; n < VOCAB; n += 512) m = fmaxf(m, lg[n]);
#pragma unroll
    for (int o = 16; o; o >>= 1) m = fmaxf(m, __shfl_xor_sync(0xffffffffu, m, o));
    if ((tid & 31) == 0) red[tid >> 5] = m;
    __syncthreads();
    if (tid < 32) {
        float v = (tid < 16) ? red[tid] : -1e30f;
#pragma unroll
        for (int o = 16; o; o >>= 1) v = fmaxf(v, __shfl_xor_sync(0xffffffffu, v, o));
        if (tid == 0) red[0] = v;
    }
    __syncthreads();
    float mx = red[0];
    __syncthreads();

    float s = 0.f;
    for (int n = tid; n < VOCAB; n += 512) {
        float e = __expf(lg[n] - mx);
        dst[n] = e;
        s += e;
    }
#pragma unroll
    for (int o = 16; o; o >>= 1) s += __shfl_xor_sync(0xffffffffu, s, o);
    if ((tid & 31) == 0) red[tid >> 5] = s;
    __syncthreads();
    if (tid < 32) {
        float v = (tid < 16) ? red[tid] : 0.f;
#pragma unroll
        for (int o = 16; o; o >>= 1) v += __shfl_xor_sync(0xffffffffu, v, o);
        if (tid == 0) red[0] = v;
    }
    __syncthreads();
    float inv = 1.f / red[0];
    for (int n = tid; n < VOCAB; n += 512) dst[n] *= inv;
}

// ---------------- launcher ---------------------------------------------------
extern "C" void kernel_launch(void* const* d_in, const int* in_sizes, int n_in,
                              void* d_out, int out_size) {
    const int*   y      = (const int*)d_in[0];
    const float* s_t_1  = (const float*)d_in[2];   // [1,B,H]
    const float* enc    = (const float*)d_in[3];   // [B,TK,H]
    const float* c_t_1  = (const float*)d_in[4];
    const float* cov    = (const float*)d_in[5];
    const float* emb    = (const float*)d_in[7];
    const float* xc_w   = (const float*)d_in[8];
    const float* xc_b   = (const float*)d_in[9];
    const float* Wh_w   = (const float*)d_in[10];
    const float* w_ih   = (const float*)d_in[11];
    const float* w_hh   = (const float*)d_in[12];
    const float* b_ih   = (const float*)d_in[13];
    const float* b_hh   = (const float*)d_in[14];
    const float* dp_w   = (const float*)d_in[15];
    const float* dp_b   = (const float*)d_in[16];
    const float* v_w    = (const float*)d_in[17];
    const float* out1_w = (const float*)d_in[18];
    const float* out1_b = (const float*)d_in[19];
    const float* out2_w = (const float*)d_in[20];
    const float* out2_b = (const float*)d_in[21];

    float* out      = (float*)d_out;
    float* out_fd   = out;                               // [B,V]
    float* out_st   = out_fd + (size_t)BB * VOCAB;       // [1,B,H]
    float* out_ct   = out_st + BB * HH;                  // [B,H]
    float* out_attn = out_ct + BB * HH;                  // [B,TK]
    float* out_cov  = out_attn + BB * TKK;               // [B,TK]

    float *p_xin, *p_x, *p_gi, *p_gh, *p_dec, *p_hnew, *p_concat, *p_out1;
    cudaGetSymbolAddress((void**)&p_xin,    g_xin);
    cudaGetSymbolAddress((void**)&p_x,      g_x);
    cudaGetSymbolAddress((void**)&p_gi,     g_gi);
    cudaGetSymbolAddress((void**)&p_gh,     g_gh);
    cudaGetSymbolAddress((void**)&p_dec,    g_dec);
    cudaGetSymbolAddress((void**)&p_hnew,   g_hnew);
    cudaGetSymbolAddress((void**)&p_concat, g_concat);
    cudaGetSymbolAddress((void**)&p_out1,   g_out1);

    // x = [c_t_1 | emb[y]] @ xc_w^T + xc_b
    k_build_xin<<<BB, 256>>>(y, c_t_1, emb);
    k_dots<<<dim3(2, BB), 128>>>(p_x, p_xin, xc_w, xc_b, EE, HH + EE);
    // GRU
    k_dots<<<dim3(12, BB), 128>>>(p_gi, p_x, w_ih, b_ih, 3 * HH, EE);
    k_dots<<<dim3(12, BB), 128>>>(p_gh, s_t_1, w_hh, b_hh, 3 * HH, HH);
    k_gru<<<BB, HH>>>(s_t_1, out_st);
    // attention
    k_dots<<<dim3(4, BB), 128>>>(p_dec, p_hnew, dp_w, dp_b, HH, HH);
    k_encfeat<<<dim3(HH / 64, M_ENC / 64), 128>>>(enc, Wh_w);
    k_scores<<<M_ENC / 8, 256>>>(v_w);
    k_attn<<<BB, 1024>>>(out_attn);
    k_ct_part<<<dim3(16, BB), 512>>>(enc, out_attn);
    k_ct_fin<<<BB, 512>>>(out_ct);
    // vocab projection
    k_dots<<<dim3(4, BB), 128>>>(p_out1, p_concat, out1_w, out1_b, HH, 2 * HH);
    cudaFuncSetAttribute(k_logits, cudaFuncAttributeMaxDynamicSharedMemorySize, 65536);
    k_logits<<<(VOCAB + 255) / 256, 256, 65536>>>(out2_w, out2_b);
    k_softmaxV<<<BB, 512>>>(out_fd);
    // coverage passthrough
    cudaMemcpyAsync(out_cov, cov, (size_t)BB * TKK * sizeof(float),
                    cudaMemcpyDeviceToDevice, 0);
}

// round 2
// speedup vs baseline: 1.3056x; 1.3056x over previous
#include <cuda_runtime.h>
#include <cuda_bf16.h>
#include <mma.h>
#include <cstddef>

using namespace nvcuda;

#define BB    32
#define TKK   1024
#define HH    512
#define EE    256
#define VOCAB 50257
#define M_ENC (BB * TKK)   // 32768

// ---------------- scratch (__device__ globals) ------------------------------
__device__ float g_xin[BB * (HH + EE)];
__device__ float g_x[BB * EE];
__device__ float g_gi[BB * 3 * HH];
__device__ float g_gh[BB * 3 * HH];
__device__ float g_hnew[BB * HH];
__device__ float g_dec[BB * HH];
__device__ float g_scores[BB * TKK];
__device__ float g_cpart[BB * 16 * HH];
__device__ float g_concat[BB * 2 * HH];
__device__ float g_out1[BB * HH];
__device__ float g_logits[(size_t)BB * VOCAB];

__device__ __forceinline__ float sigmoidf_(float x) { return 1.f / (1.f + __expf(-x)); }
__device__ __forceinline__ float tanh_fast(float x) {
    float r; asm("tanh.approx.f32 %0, %1;" : "=f"(r) : "f"(x)); return r;
}

// ---------------- K1: build [c_t_1 | emb[y]] --------------------------------
__global__ void k_build_xin(const int* __restrict__ yt,
                            const float* __restrict__ c_t_1,
                            const float* __restrict__ emb) {
    int b = blockIdx.x;
    int yid = yt[b];
    for (int i = threadIdx.x; i < HH; i += blockDim.x)
        g_xin[b * (HH + EE) + i] = c_t_1[b * HH + i];
    for (int i = threadIdx.x; i < EE; i += blockDim.x)
        g_xin[b * (HH + EE) + HH + i] = emb[(size_t)yid * EE + i];
}

// ---------------- batched small GEMM: y[b,n] = bias[n] + A[b,:].W[n,:] ------
// warp = one n, lanes = 32 batches. A staged transposed in smem; W read once.
__global__ __launch_bounds__(256) void k_bdots(float* __restrict__ y,
                                               const float* __restrict__ A,
                                               const float* __restrict__ W,
                                               const float* __restrict__ bias,
                                               int N, int K) {
    extern __shared__ float sA[];   // [K][33]  (padded, transposed)
    int tid = threadIdx.x;
    for (int idx = tid; idx < BB * K; idx += 256) {
        int b = idx / K, k = idx - b * K;
        sA[k * 33 + b] = A[idx];
    }
    __syncthreads();
    int warp = tid >> 5, lane = tid & 31;
    int n = blockIdx.x * 8 + warp;
    const float4* wr4 = (const float4*)(W + (size_t)n * K);
    float acc = 0.f;
    int K4 = K >> 2;
#pragma unroll 4
    for (int k4 = 0; k4 < K4; k4++) {
        float4 w = wr4[k4];                 // uniform broadcast load
        const float* a0 = sA + (k4 * 4) * 33 + lane;
        acc += w.x * a0[0] + w.y * a0[33] + w.z * a0[66] + w.w * a0[99];
    }
    y[(size_t)lane * N + n] = acc + bias[n];
}

// ---------------- GRU gate combine ------------------------------------------
__global__ void k_gru(const float* __restrict__ hprev, float* __restrict__ out_st) {
    int b = blockIdx.x, j = threadIdx.x;   // 512 threads
    const float* gi = g_gi + b * 3 * HH;
    const float* gh = g_gh + b * 3 * HH;
    float r  = sigmoidf_(gi[j] + gh[j]);
    float z  = sigmoidf_(gi[HH + j] + gh[HH + j]);
    float nn = tanhf(gi[2 * HH + j] + r * gh[2 * HH + j]);
    float h  = hprev[b * HH + j];
    float hn = (1.f - z) * nn + z * h;
    g_hnew[b * HH + j] = hn;
    out_st[b * HH + j] = hn;
}

// ---------------- fused: scores = v . tanh(enc@Wh^T + dec)  -----------------
// block: 512 threads (16 warps), tile M=64 rows x N=512 (full H), K=512.
// Epilogue consumes the GEMM tile in smem -> no 64MB scratch round trip.
__global__ __launch_bounds__(512) void k_fused_attn(const float* __restrict__ enc,
                                                    const float* __restrict__ Wh,
                                                    const float* __restrict__ vw) {
    extern __shared__ char smraw[];
    float* stage = (float*)smraw;                       // [64][520]
    float* sdec  = stage + 64 * 520;                    // [512]
    float* sv    = sdec + 512;                          // [512]
    __nv_bfloat16* As = (__nv_bfloat16*)(sv + 512);     // [64][40]
    __nv_bfloat16* Bs = As + 64 * 40;                   // [512][40]

    int tid = threadIdx.x, warp = tid >> 5, lane = tid & 31;
    int bt = blockIdx.x;                // 0..511
    int b  = bt >> 4;
    size_t m0 = (size_t)bt * 64;

    sdec[tid] = g_dec[b * HH + tid];
    sv[tid]   = vw[tid];

    int wm = warp >> 3, wn = warp & 7;  // warp tile: rows wm*32(+32), cols wn*64(+64)
    wmma::fragment<wmma::accumulator, 16, 16, 16, float> acc[2][4];
#pragma unroll
    for (int i = 0; i < 2; i++)
#pragma unroll
        for (int j = 0; j < 4; j++) wmma::fill_fragment(acc[i][j], 0.f);

    int arow = tid >> 3, aq = tid & 7;
    for (int k0 = 0; k0 < HH; k0 += 32) {
        // A slice 64x32
        float4 va = *(const float4*)(enc + (m0 + arow) * HH + k0 + aq * 4);
        *(__nv_bfloat162*)&As[arow * 40 + aq * 4]     = __floats2bfloat162_rn(va.x, va.y);
        *(__nv_bfloat162*)&As[arow * 40 + aq * 4 + 2] = __floats2bfloat162_rn(va.z, va.w);
        // B slice 512x32 (8 passes of 64 rows)
#pragma unroll
        for (int p = 0; p < 8; p++) {
            int row = p * 64 + arow;
            float4 vb = *(const float4*)(Wh + (size_t)row * HH + k0 + aq * 4);
            *(__nv_bfloat162*)&Bs[row * 40 + aq * 4]     = __floats2bfloat162_rn(vb.x, vb.y);
            *(__nv_bfloat162*)&Bs[row * 40 + aq * 4 + 2] = __floats2bfloat162_rn(vb.z, vb.w);
        }
        __syncthreads();
#pragma unroll
        for (int kk = 0; kk < 32; kk += 16) {
            wmma::fragment<wmma::matrix_a, 16, 16, 16, __nv_bfloat16, wmma::row_major> af[2];
#pragma unroll
            for (int i = 0; i < 2; i++)
                wmma::load_matrix_sync(af[i], As + (wm * 32 + i * 16) * 40 + kk, 40);
#pragma unroll
            for (int j = 0; j < 4; j++) {
                wmma::fragment<wmma::matrix_b, 16, 16, 16, __nv_bfloat16, wmma::col_major> bf;
                wmma::load_matrix_sync(bf, Bs + (wn * 64 + j * 16) * 40 + kk, 40);
                wmma::mma_sync(acc[0][j], af[0], bf, acc[0][j]);
                wmma::mma_sync(acc[1][j], af[1], bf, acc[1][j]);
            }
        }
        __syncthreads();
    }
    // dump tile to smem
#pragma unroll
    for (int i = 0; i < 2; i++)
#pragma unroll
        for (int j = 0; j < 4; j++)
            wmma::store_matrix_sync(stage + (wm * 32 + i * 16) * 520 + wn * 64 + j * 16,
                                    acc[i][j], 520, wmma::mem_row_major);
    __syncthreads();
    // epilogue: per row, score = sum_n v[n]*tanh(stage+dec)
#pragma unroll
    for (int rr = 0; rr < 4; rr++) {
        int r = warp * 4 + rr;
        const float* sr = stage + r * 520;
        float a = 0.f;
#pragma unroll
        for (int it = 0; it < 16; it++) {
            int n = lane + it * 32;
            a += sv[n] * tanh_fast(sr[n] + sdec[n]);
        }
#pragma unroll
        for (int o = 16; o; o >>= 1) a += __shfl_down_sync(0xffffffffu, a, o);
        if (lane == 0) g_scores[bt * 64 + r] = a;
    }
}

// ---------------- softmax over TK per b -------------------------------------
__global__ void k_attn(float* __restrict__ out_attn) {
    __shared__ float red[32];
    int b = blockIdx.x, t = threadIdx.x;   // 1024 threads
    float s = g_scores[b * TKK + t];
    float m = s;
#pragma unroll
    for (int o = 16; o; o >>= 1) m = fmaxf(m, __shfl_xor_sync(0xffffffffu, m, o));
    if ((t & 31) == 0) red[t >> 5] = m;
    __syncthreads();
    if (t < 32) {
        float v = red[t];
#pragma unroll
        for (int o = 16; o; o >>= 1) v = fmaxf(v, __shfl_xor_sync(0xffffffffu, v, o));
        if (t == 0) red[0] = v;
    }
    __syncthreads();
    float mx = red[0];
    __syncthreads();
    float e = __expf(s - mx);
    float sm = e;
#pragma unroll
    for (int o = 16; o; o >>= 1) sm += __shfl_xor_sync(0xffffffffu, sm, o);
    if ((t & 31) == 0) red[t >> 5] = sm;
    __syncthreads();
    if (t < 32) {
        float v = red[t];
#pragma unroll
        for (int o = 16; o; o >>= 1) v += __shfl_xor_sync(0xffffffffu, v, o);
        if (t == 0) red[0] = v;
    }
    __syncthreads();
    out_attn[b * TKK + t] = e * (1.f / red[0]);
}

// ---------------- c_t partials ----------------------------------------------
__global__ void k_ct_part(const float* __restrict__ enc, const float* __restrict__ attn) {
    __shared__ float sa[64];
    int c = blockIdx.x, b = blockIdx.y, h = threadIdx.x;   // 512 threads
    if (h < 64) sa[h] = attn[b * TKK + c * 64 + h];
    __syncthreads();
    const float* e = enc + ((size_t)b * TKK + c * 64) * HH + h;
    float acc = 0.f;
#pragma unroll 8
    for (int t = 0; t < 64; t++) acc += sa[t] * e[(size_t)t * HH];
    g_cpart[((size_t)b * 16 + c) * HH + h] = acc;
}

__global__ void k_ct_fin(float* __restrict__ out_ct) {
    int b = blockIdx.x, h = threadIdx.x;   // 512
    float acc = 0.f;
#pragma unroll
    for (int c = 0; c < 16; c++) acc += g_cpart[((size_t)b * 16 + c) * HH + h];
    out_ct[b * HH + h] = acc;
    g_concat[b * 2 * HH + h] = g_hnew[b * HH + h];
    g_concat[b * 2 * HH + HH + h] = acc;
}

// ---------------- logits via wmma: [32 x V] = out1[32,512] @ W[V,512]^T -----
__global__ __launch_bounds__(256) void k_logits_mma(const float* __restrict__ W,
                                                    const float* __restrict__ bias) {
    extern __shared__ char smraw[];
    float* stage = (float*)smraw;                         // [32][136]
    __nv_bfloat16* As2 = (__nv_bfloat16*)(stage + 32 * 136);  // [32][520]
    __nv_bfloat16* Ws  = As2 + 32 * 520;                  // [128][40]

    int tid = threadIdx.x, warp = tid >> 5;
    int n0 = blockIdx.x * 128;
    // stage A = bf16(out1)
    for (int idx = tid; idx < BB * HH; idx += 256) {
        int r = idx >> 9, k = idx & 511;
        As2[r * 520 + k] = __float2bfloat16(g_out1[idx]);
    }
    __syncthreads();

    wmma::fragment<wmma::accumulator, 16, 16, 16, float> acc[2];
    wmma::fill_fragment(acc[0], 0.f);
    wmma::fill_fragment(acc[1], 0.f);

    int lrow = tid >> 3, lq = tid & 7;
    for (int k0 = 0; k0 < HH; k0 += 32) {
#pragma unroll
        for (int p = 0; p < 4; p++) {
            int row = p * 32 + lrow;
            int n = n0 + row;
            float4 w = make_float4(0.f, 0.f, 0.f, 0.f);
            if (n < VOCAB) w = *(const float4*)(W + (size_t)n * HH + k0 + lq * 4);
            *(__nv_bfloat162*)&Ws[row * 40 + lq * 4]     = __floats2bfloat162_rn(w.x, w.y);
            *(__nv_bfloat162*)&Ws[row * 40 + lq * 4 + 2] = __floats2bfloat162_rn(w.z, w.w);
        }
        __syncthreads();
#pragma unroll
        for (int kk = 0; kk < 32; kk += 16) {
            wmma::fragment<wmma::matrix_b, 16, 16, 16, __nv_bfloat16, wmma::col_major> bf;
            wmma::load_matrix_sync(bf, Ws + (warp * 16) * 40 + kk, 40);
#pragma unroll
            for (int i = 0; i < 2; i++) {
                wmma::fragment<wmma::matrix_a, 16, 16, 16, __nv_bfloat16, wmma::row_major> af;
                wmma::load_matrix_sync(af, As2 + (i * 16) * 520 + k0 + kk, 520);
                wmma::mma_sync(acc[i], af, bf, acc[i]);
            }
        }
        __syncthreads();
    }
#pragma unroll
    for (int i = 0; i < 2; i++)
        wmma::store_matrix_sync(stage + (i * 16) * 136 + warp * 16, acc[i], 136,
                                wmma::mem_row_major);
    __syncthreads();
    for (int idx = tid; idx < 32 * 128; idx += 256) {
        int r = idx >> 7, c = idx & 127;
        int n = n0 + c;
        if (n < VOCAB)
            g_logits[(size_t)r * VOCAB + n] = stage[r * 136 + c] + bias[n];
    }
}

// ---------------- softmax over V per b --------------------------------------
__global__ void k_softmaxV(float* __restrict__ out_fd) {
    __shared__ float red[32];
    int b = blockIdx.x, tid = threadIdx.x;     // 512 threads
    const float* lg = g_logits + (size_t)b * VOCAB;
    float* dst = out_fd + (size_t)b * VOCAB;

    float m = -1e30f;
    for (int n = tid; n < VOCAB; n += 512) m = fmaxf(m, lg[n]);
#pragma unroll
    for (int o = 16; o; o >>= 1) m = fmaxf(m, __shfl_xor_sync(0xffffffffu, m, o));
    if ((tid & 31) == 0) red[tid >> 5] = m;
    __syncthreads();
    if (tid < 32) {
        float v = (tid < 16) ? red[tid] : -1e30f;
#pragma unroll
        for (int o = 16; o; o >>= 1) v = fmaxf(v, __shfl_xor_sync(0xffffffffu, v, o));
        if (tid == 0) red[0] = v;
    }
    __syncthreads();
    float mx = red[0];
    __syncthreads();

    float s = 0.f;
    for (int n = tid; n < VOCAB; n += 512) {
        float e = __expf(lg[n] - mx);
        dst[n] = e;
        s += e;
    }
#pragma unroll
    for (int o = 16; o; o >>= 1) s += __shfl_xor_sync(0xffffffffu, s, o);
    if ((tid & 31) == 0) red[tid >> 5] = s;
    __syncthreads();
    if (tid < 32) {
        float v = (tid < 16) ? red[tid] : 0.f;
#pragma unroll
        for (int o = 16; o; o >>= 1) v += __shfl_xor_sync(0xffffffffu, v, o);
        if (tid == 0) red[0] = v;
    }
    __syncthreads();
    float inv = 1.f / red[0];
    for (int n = tid; n < VOCAB; n += 512) dst[n] *= inv;
}

// ---------------- launcher ---------------------------------------------------
extern "C" void kernel_launch(void* const* d_in, const int* in_sizes, int n_in,
                              void* d_out, int out_size) {
    const int*   y      = (const int*)d_in[0];
    const float* s_t_1  = (const float*)d_in[2];
    const float* enc    = (const float*)d_in[3];
    const float* c_t_1  = (const float*)d_in[4];
    const float* cov    = (const float*)d_in[5];
    const float* emb    = (const float*)d_in[7];
    const float* xc_w   = (const float*)d_in[8];
    const float* xc_b   = (const float*)d_in[9];
    const float* Wh_w   = (const float*)d_in[10];
    const float* w_ih   = (const float*)d_in[11];
    const float* w_hh   = (const float*)d_in[12];
    const float* b_ih   = (const float*)d_in[13];
    const float* b_hh   = (const float*)d_in[14];
    const float* dp_w   = (const float*)d_in[15];
    const float* dp_b   = (const float*)d_in[16];
    const float* v_w    = (const float*)d_in[17];
    const float* out1_w = (const float*)d_in[18];
    const float* out1_b = (const float*)d_in[19];
    const float* out2_w = (const float*)d_in[20];
    const float* out2_b = (const float*)d_in[21];

    float* out      = (float*)d_out;
    float* out_fd   = out;                               // [B,V]
    float* out_st   = out_fd + (size_t)BB * VOCAB;       // [1,B,H]
    float* out_ct   = out_st + BB * HH;                  // [B,H]
    float* out_attn = out_ct + BB * HH;                  // [B,TK]
    float* out_cov  = out_attn + BB * TKK;               // [B,TK]

    float *p_xin, *p_x, *p_gi, *p_gh, *p_dec, *p_hnew, *p_concat, *p_out1;
    cudaGetSymbolAddress((void**)&p_xin,    g_xin);
    cudaGetSymbolAddress((void**)&p_x,      g_x);
    cudaGetSymbolAddress((void**)&p_gi,     g_gi);
    cudaGetSymbolAddress((void**)&p_gh,     g_gh);
    cudaGetSymbolAddress((void**)&p_dec,    g_dec);
    cudaGetSymbolAddress((void**)&p_hnew,   g_hnew);
    cudaGetSymbolAddress((void**)&p_concat, g_concat);
    cudaGetSymbolAddress((void**)&p_out1,   g_out1);

    static int attrs_done = 0;
    if (!attrs_done) {
        cudaFuncSetAttribute(k_bdots, cudaFuncAttributeMaxDynamicSharedMemorySize,
                             1024 * 33 * 4);
        cudaFuncSetAttribute(k_fused_attn, cudaFuncAttributeMaxDynamicSharedMemorySize,
                             183296);
        cudaFuncSetAttribute(k_logits_mma, cudaFuncAttributeMaxDynamicSharedMemorySize,
                             32 * 136 * 4 + 32 * 520 * 2 + 128 * 40 * 2);
        attrs_done = 1;
    }

    // front-end chain
    k_build_xin<<<BB, 256>>>(y, c_t_1, emb);
    k_bdots<<<EE / 8, 256, (HH + EE) * 33 * 4>>>(p_x, p_xin, xc_w, xc_b, EE, HH + EE);
    k_bdots<<<3 * HH / 8, 256, HH * 33 * 4>>>(p_gh, s_t_1, w_hh, b_hh, 3 * HH, HH);
    k_bdots<<<3 * HH / 8, 256, EE * 33 * 4>>>(p_gi, p_x, w_ih, b_ih, 3 * HH, EE);
    k_gru<<<BB, HH>>>(s_t_1, out_st);
    k_bdots<<<HH / 8, 256, HH * 33 * 4>>>(p_dec, p_hnew, dp_w, dp_b, HH, HH);
    // fused attention scores
    k_fused_attn<<<M_ENC / 64, 512, 183296>>>(enc, Wh_w, v_w);
    k_attn<<<BB, 1024>>>(out_attn);
    k_ct_part<<<dim3(16, BB), 512>>>(enc, out_attn);
    k_ct_fin<<<BB, 512>>>(out_ct);
    // vocab projection
    k_bdots<<<HH / 8, 256, 2 * HH * 33 * 4>>>(p_out1, p_concat, out1_w, out1_b, HH, 2 * HH);
    k_logits_mma<<<(VOCAB + 127) / 128, 256,
                   32 * 136 * 4 + 32 * 520 * 2 + 128 * 40 * 2>>>(out2_w, out2_b);
    k_softmaxV<<<BB, 512>>>(out_fd);
    // coverage passthrough
    cudaMemcpyAsync(out_cov, cov, (size_t)BB * TKK * sizeof(float),
                    cudaMemcpyDeviceToDevice, 0);
}